// round 13
// baseline (speedup 1.0000x reference)
#include <cuda_runtime.h>
#include <cstdint>

#define H 256
#define B 32
#define S 1024
#define NL 4
#define NE (H * B)              // 8192
#define G4 (4 * H)              // 1024
#define MROWS (S * B)           // 32768
#define LSTRIDE ((S + 1) * NE)  // per-layer h0/c0 slab stride

// -------- static scratch (allowed: __device__ globals) --------
__device__ float g_gates[(size_t)MROWS * G4];   // 128 MB: [t*B+b][4H]
__device__ float g_xbuf0[(size_t)MROWS * H];    // 32 MB:  [t*B+b][H]
__device__ float g_xbuf1[(size_t)MROWS * H];    // 32 MB

// -------- helpers --------
__device__ __forceinline__ void ffma2(unsigned long long& d,
                                      unsigned long long a,
                                      unsigned long long b) {
    asm("fma.rn.f32x2 %0, %1, %2, %0;" : "+l"(d) : "l"(a), "l"(b));
}
__device__ __forceinline__ unsigned long long dup2(float a) {
    unsigned long long r;
    asm("mov.b64 %0, {%1, %1};" : "=l"(r) : "f"(a));
    return r;
}
__device__ __forceinline__ float2 unpack2(unsigned long long v) {
    float2 f;
    asm("mov.b64 {%0, %1}, %2;" : "=f"(f.x), "=f"(f.y) : "l"(v));
    return f;
}
__device__ __forceinline__ uint32_t smem_u32(const void* p) {
    return (uint32_t)__cvta_generic_to_shared(p);
}
__device__ __forceinline__ uint32_t ctarank() {
    uint32_t r;
    asm("mov.u32 %0, %%cluster_ctarank;" : "=r"(r));
    return r;
}
__device__ __forceinline__ uint32_t mapa_rank(uint32_t laddr, int r) {
    uint32_t ra;
    asm("mapa.shared::cluster.u32 %0, %1, %2;" : "=r"(ra) : "r"(laddr), "r"(r));
    return ra;
}
// fast, branch-free activations (rel err ~1e-6; saturate correctly)
__device__ __forceinline__ float fsigm(float x) {
    return __fdividef(1.0f, 1.0f + __expf(-x));
}
__device__ __forceinline__ float ftanh(float x) {
    return __fdividef(2.0f, 1.0f + __expf(-2.0f * x)) - 1.0f;
}
__device__ __forceinline__ void mbar_init(uint32_t a, int cnt) {
    asm volatile("mbarrier.init.shared.b64 [%0], %1;" :: "r"(a), "r"(cnt) : "memory");
}
__device__ __forceinline__ void mbar_expect(uint32_t a, uint32_t bytes) {
    asm volatile("mbarrier.arrive.expect_tx.shared.b64 _, [%0], %1;"
                 :: "r"(a), "r"(bytes) : "memory");
}
// 256-B CTA->peer-CTA smem bulk copy; ONE tx update of 256 B at the
// destination CTA's mbarrier (vs 32 st.async updates).
__device__ __forceinline__ void bulk_s2s(uint32_t dst, uint32_t src,
                                         uint32_t bytes, uint32_t rbar) {
    asm volatile(
        "cp.async.bulk.shared::cluster.shared::cta.mbarrier::complete_tx::bytes "
        "[%0], [%1], %2, [%3];"
        :: "r"(dst), "r"(src), "r"(bytes), "r"(rbar) : "memory");
}
__device__ __forceinline__ void fence_proxy_async_cta() {
    asm volatile("fence.proxy.async.shared::cta;" ::: "memory");
}
__device__ __forceinline__ void mbar_wait(uint32_t a, uint32_t parity) {
    uint32_t done;
    asm volatile(
        "{\n\t.reg .pred p;\n\t"
        "mbarrier.try_wait.parity.acquire.cta.shared::cta.b64 p, [%1], %2;\n\t"
        "selp.b32 %0, 1, 0, p;\n\t}"
        : "=r"(done) : "r"(a), "r"(parity) : "memory");
    if (!done) {
        asm volatile(
            "{\n\t.reg .pred P1;\n\t"
            "W_%=:\n\t"
            "mbarrier.try_wait.parity.acquire.cta.shared::cta.b64 P1, [%0], %1, 0x989680;\n\t"
            "@P1 bra.uni D_%=;\n\t"
            "bra.uni W_%=;\n\t"
            "D_%=:\n\t}"
            :: "r"(a), "r"(parity) : "memory");
    }
}

// ============================================================
// GEMM: C[M=32768, N=1024] = A[M,256] @ W^T + bias
// BM=128, BN=128, BK=16, 256 threads, 8x8 microtile, FFMA2.
// ============================================================
__global__ void __launch_bounds__(256, 2)
lstm_gemm(const float* __restrict__ Aex, int asel,
          const float* __restrict__ Wl,
          const float* __restrict__ bl)
{
    const float* A = (asel == 0) ? Aex : (asel == 1 ? g_xbuf0 : g_xbuf1);
    float* Cout = g_gates;

    __shared__ __align__(16) float As[16][128];
    __shared__ __align__(16) float Bs[16][128];

    const int tid = threadIdx.x;
    const int n0 = blockIdx.x * 128;
    const int m0 = blockIdx.y * 128;
    const int tx = tid & 15, ty = tid >> 4;

    const int lr = tid >> 2;        // 0..63
    const int lk4 = tid & 3;        // 0..3

    unsigned long long acc[8][4];
#pragma unroll
    for (int i = 0; i < 8; i++)
#pragma unroll
        for (int j = 0; j < 4; j++) acc[i][j] = 0ull;

    const float* aP0 = A  + (size_t)(m0 + lr)      * 256 + lk4 * 4;
    const float* aP1 = A  + (size_t)(m0 + lr + 64) * 256 + lk4 * 4;
    const float* bP0 = Wl + (size_t)(n0 + lr)      * 256 + lk4 * 4;
    const float* bP1 = Wl + (size_t)(n0 + lr + 64) * 256 + lk4 * 4;

    float4 a0 = *(const float4*)(aP0);
    float4 a1 = *(const float4*)(aP1);
    float4 w0 = *(const float4*)(bP0);
    float4 w1 = *(const float4*)(bP1);

    for (int kt = 0; kt < 256; kt += 16) {
        __syncthreads();
        {
            int kb = lk4 * 4;
            As[kb + 0][lr] = a0.x; As[kb + 1][lr] = a0.y;
            As[kb + 2][lr] = a0.z; As[kb + 3][lr] = a0.w;
            As[kb + 0][lr + 64] = a1.x; As[kb + 1][lr + 64] = a1.y;
            As[kb + 2][lr + 64] = a1.z; As[kb + 3][lr + 64] = a1.w;
            Bs[kb + 0][lr] = w0.x; Bs[kb + 1][lr] = w0.y;
            Bs[kb + 2][lr] = w0.z; Bs[kb + 3][lr] = w0.w;
            Bs[kb + 0][lr + 64] = w1.x; Bs[kb + 1][lr + 64] = w1.y;
            Bs[kb + 2][lr + 64] = w1.z; Bs[kb + 3][lr + 64] = w1.w;
        }
        __syncthreads();

        if (kt < 240) {
            a0 = *(const float4*)(aP0 + kt + 16);
            a1 = *(const float4*)(aP1 + kt + 16);
            w0 = *(const float4*)(bP0 + kt + 16);
            w1 = *(const float4*)(bP1 + kt + 16);
        }

#pragma unroll
        for (int k = 0; k < 16; k++) {
            unsigned long long b2[4];
#pragma unroll
            for (int j = 0; j < 4; j++)
                b2[j] = *(const unsigned long long*)&Bs[k][tx * 8 + 2 * j];
            float4 af0 = *(const float4*)&As[k][ty * 8];
            float4 af1 = *(const float4*)&As[k][ty * 8 + 4];
            float a[8] = {af0.x, af0.y, af0.z, af0.w, af1.x, af1.y, af1.z, af1.w};
#pragma unroll
            for (int i = 0; i < 8; i++) {
                unsigned long long a2 = dup2(a[i]);
#pragma unroll
                for (int j = 0; j < 4; j++) ffma2(acc[i][j], a2, b2[j]);
            }
        }
    }

    float bias_r[8];
#pragma unroll
    for (int j = 0; j < 8; j++) bias_r[j] = bl[n0 + tx * 8 + j];
#pragma unroll
    for (int i = 0; i < 8; i++) {
        float o[8];
#pragma unroll
        for (int j = 0; j < 4; j++) {
            float2 v = unpack2(acc[i][j]);
            o[2 * j + 0] = v.x + bias_r[2 * j + 0];
            o[2 * j + 1] = v.y + bias_r[2 * j + 1];
        }
        float* crow = Cout + (size_t)(m0 + ty * 8 + i) * G4 + n0 + tx * 8;
        *(float4*)(crow + 0) = make_float4(o[0], o[1], o[2], o[3]);
        *(float4*)(crow + 4) = make_float4(o[4], o[5], o[6], o[7]);
    }
}

// ============================================================
// Recurrence scan. 16 clusters x 8 CTAs, 256 thr. Cluster owns
// batches {2c,2c+1}; CTA rank owns 32 h-indices x 4 gates (R in
// registers). Exchange: each CTA stages its 64 new h values
// (256 B) and issues 8 cp.async.bulk S2S copies (one per rank)
// completing the destination's transaction mbarrier -> only 8
// tx-updates per barrier per step (vs 256 st.async updates).
// hs layout [buf][srcrank][batch][32] keeps each source's slice
// contiguous. hnew is step-parity double-buffered so the bulk
// engine's src read (step t) is provably done before the t+2
// overwrite (my wait(t+1) implies peers received step t).
// ============================================================
__global__ void __launch_bounds__(256, 1) __cluster_dims__(8, 1, 1)
lstm_scan(const float* __restrict__ Rl,
          const float* __restrict__ h0,
          const float* __restrict__ c0,
          float* __restrict__ xex, int osel)
{
    float* xnext = (osel == 2) ? xex : (osel == 0 ? g_xbuf0 : g_xbuf1);
    const float* gates = g_gates;

    __shared__ __align__(16) float hs[2][8][2][32];    // buf, srcrank, b, j
    __shared__ __align__(16) float gxs[2][2][4][32];   // parity, b, gate, jj
    __shared__ __align__(16) float hnew[2][2][32];     // parity, b, jj (256 B each)
    __shared__ __align__(8) unsigned long long mbars[2];

    const int tid = threadIdx.x;
    const int rank = (int)ctarank();
    const int b0 = (blockIdx.x >> 3) * 2;
    const int sub = tid & 7;
    const int jj = tid >> 3;
    const int hidx = rank * 32 + jj;

    // ---- register-resident R slice: 4 gates x 16 column pairs ----
    unsigned long long Rf[4][16];
#pragma unroll
    for (int g = 0; g < 4; g++) {
        const float* base = Rl + (size_t)(g * 256 + hidx) * 256;
#pragma unroll
        for (int k2 = 0; k2 < 16; k2++)
            Rf[g][k2] = *(const unsigned long long*)(base + sub * 2 + 16 * k2);
    }

    // ---- initial h into hs[0] (new layout) and c (owner regs) ----
    for (int i = tid; i < 512; i += 256) {
        int r = i >> 6, b = (i >> 5) & 1, j = i & 31;
        hs[0][r][b][j] = h0[(size_t)(b0 + b) * H + r * 32 + j];
    }
    const int myb = sub;                 // meaningful for sub < 2
    const bool is_owner = (sub < 2);
    float creg = 0.f;
    if (is_owner) creg = c0[(size_t)(b0 + myb) * H + hidx];

    // gate-x loader role (one value per step per thread)
    const int gb = tid >> 7;
    const int grem = tid & 127;
    const int gg_ = grem >> 5;
    const int gj = grem & 31;
    const size_t gcol = (size_t)(gg_ * 256 + rank * 32 + gj);
    gxs[0][gb][gg_][gj] = gates[(size_t)(b0 + gb) * G4 + gcol];  // t = 0

    // ---- loop-invariant bulk-copy addresses (threads tid < 8) ----
    const uint32_t lmb0 = smem_u32((const void*)&mbars[0]);
    const uint32_t lmb1 = smem_u32((const void*)&mbars[1]);
    uint32_t dstA = 0, dstB = 0, rmb0 = 0, rmb1 = 0;
    if (tid < 8) {
        dstA = mapa_rank(smem_u32(&hs[1][rank][0][0]), tid);  // my slice, buf 1
        dstB = mapa_rank(smem_u32(&hs[0][rank][0][0]), tid);  // my slice, buf 0
        rmb0 = mapa_rank(lmb0, tid);
        rmb1 = mapa_rank(lmb1, tid);
    }
    const uint32_t srcH0 = smem_u32(&hnew[0][0][0]);
    const uint32_t srcH1 = smem_u32(&hnew[1][0][0]);

    if (tid == 0) {
        mbar_init(lmb0, 1);
        mbar_init(lmb1, 1);
        mbar_expect(lmb0, 2048);   // expect for t = 0
    }
    __syncthreads();
    asm volatile("barrier.cluster.arrive.aligned;" ::: "memory");
    asm volatile("barrier.cluster.wait.aligned;" ::: "memory");

    int p = 0;
    for (int t = 0; t < S; t++) {
        // prefetch next step's gates_x (hides DRAM latency under the dot)
        int t1 = (t + 1 < S) ? (t + 1) : (S - 1);
        float gnext = gates[(size_t)(t1 * B + b0 + gb) * G4 + gcol];

        // ---- dot: acc[g][b] over this thread's 32 columns ----
        // col = sub*2 + 16*k2 -> hs[p][k2>>1][b][sub*2 + 16*(k2&1)]
        unsigned long long acc[4][2] = {{0ull, 0ull}, {0ull, 0ull},
                                        {0ull, 0ull}, {0ull, 0ull}};
        const float* hpb = &hs[p][0][0][sub * 2];
#pragma unroll
        for (int k2 = 0; k2 < 16; k2++) {
            const int off = (k2 >> 1) * 64 + (k2 & 1) * 16;
            unsigned long long h0v = *(const unsigned long long*)(hpb + off);
            unsigned long long h1v = *(const unsigned long long*)(hpb + off + 32);
#pragma unroll
            for (int g = 0; g < 4; g++) {
                ffma2(acc[g][0], Rf[g][k2], h0v);
                ffma2(acc[g][1], Rf[g][k2], h1v);
            }
        }

        // ---- reduce over the 8-lane column group ----
        float red[4][2];
#pragma unroll
        for (int g = 0; g < 4; g++)
#pragma unroll
            for (int b = 0; b < 2; b++) {
                float2 v = unpack2(acc[g][b]);
                float s = v.x + v.y;
                s += __shfl_xor_sync(0xffffffffu, s, 1);
                s += __shfl_xor_sync(0xffffffffu, s, 2);
                s += __shfl_xor_sync(0xffffffffu, s, 4);
                red[g][b] = s;
            }

        // stage next step's gates_x
        gxs[(t + 1) & 1][gb][gg_][gj] = gnext;

        // ---- cell epilogue (two lanes per jj: sub==b) ----
        if (is_owner) {
            float gi = red[0][myb] + gxs[t & 1][myb][0][jj];
            float gf = red[1][myb] + gxs[t & 1][myb][1][jj];
            float gG = red[2][myb] + gxs[t & 1][myb][2][jj];
            float go = red[3][myb] + gxs[t & 1][myb][3][jj];
            float iv = fsigm(gi);
            float fv = fsigm(gf);
            float gv = ftanh(gG);
            float ov = fsigm(go);
            float cnew = fv * creg + iv * gv;
            creg = cnew;
            hnew[t & 1][myb][jj] = ov * ftanh(cnew);
        }
        __syncthreads();   // hnew[t&1] complete CTA-wide

        // expect for step t+1: posted a full step+flight before any peer's
        // t+1 bytes can exist (they require our step-t send below first)
        if (tid == 0) mbar_expect((t & 1) ? lmb0 : lmb1, 2048);

        // ---- 8 bulk copies: my 256-B slice -> every rank's hs[p^1] ----
        if (tid < 8) {
            fence_proxy_async_cta();   // order hnew STS into async proxy
            bulk_s2s((p == 0) ? dstA : dstB,
                     (t & 1) ? srcH1 : srcH0,
                     256,
                     (t & 1) ? rmb1 : rmb0);
        }

        // global write of this CTA's h slice (off all sync paths)
        if (tid < 16) {
            int b = tid >> 3, q = tid & 7;
            float4 v = ((const float4*)&hnew[t & 1][b][0])[q];
            *(float4*)&xnext[(size_t)(t * B + b0 + b) * H + rank * 32 + q * 4] = v;
        }

        // wait for all 8 x 256 B of step t to land in hs[p^1]
        mbar_wait((t & 1) ? lmb1 : lmb0, (uint32_t)((t >> 1) & 1));
        p ^= 1;
    }

    // keep smem alive until every peer's last copy (from our hnew) is done
    asm volatile("barrier.cluster.arrive.aligned;" ::: "memory");
    asm volatile("barrier.cluster.wait.aligned;" ::: "memory");
}

// ============================================================
// Host: 4 x (GEMM, SCAN), ping-pong x buffers, all on stream 0.
// ============================================================
extern "C" void kernel_launch(void* const* d_in, const int* in_sizes, int n_in,
                              void* d_out, int out_size)
{
    const float* h_data = (const float*)d_in[0];
    const float* x_data = (const float*)d_in[1];
    const float* c_data = (const float*)d_in[2];
    const float* W      = (const float*)d_in[3];
    const float* R      = (const float*)d_in[4];
    const float* bias   = (const float*)d_in[5];
    float* out = (float*)d_out;

    const dim3 ggrid(8, 256);               // N/128, M/128
    const size_t wstride = (size_t)G4 * H;

    lstm_gemm<<<ggrid, 256>>>(x_data, 0, W + 0 * wstride, bias + 0 * G4);
    lstm_scan<<<128, 256>>>(R + 0 * wstride,
                            h_data + 0 * (size_t)LSTRIDE,
                            c_data + 0 * (size_t)LSTRIDE,
                            nullptr, 0);
    lstm_gemm<<<ggrid, 256>>>(nullptr, 1, W + 1 * wstride, bias + 1 * G4);
    lstm_scan<<<128, 256>>>(R + 1 * wstride,
                            h_data + 1 * (size_t)LSTRIDE,
                            c_data + 1 * (size_t)LSTRIDE,
                            nullptr, 1);
    lstm_gemm<<<ggrid, 256>>>(nullptr, 2, W + 2 * wstride, bias + 2 * G4);
    lstm_scan<<<128, 256>>>(R + 2 * wstride,
                            h_data + 2 * (size_t)LSTRIDE,
                            c_data + 2 * (size_t)LSTRIDE,
                            nullptr, 0);
    lstm_gemm<<<ggrid, 256>>>(nullptr, 1, W + 3 * wstride, bias + 3 * G4);
    lstm_scan<<<128, 256>>>(R + 3 * wstride,
                            h_data + 3 * (size_t)LSTRIDE,
                            c_data + 3 * (size_t)LSTRIDE,
                            out, 2);
}

// round 15
// speedup vs baseline: 1.5338x; 1.5338x over previous
#include <cuda_runtime.h>
#include <cstdint>

#define H 256
#define B 32
#define S 1024
#define NL 4
#define NE (H * B)              // 8192
#define G4 (4 * H)              // 1024
#define MROWS (S * B)           // 32768
#define LSTRIDE ((S + 1) * NE)  // per-layer h0/c0 slab stride

// -------- static scratch (allowed: __device__ globals) --------
__device__ float g_gates[(size_t)MROWS * G4];   // 128 MB: [t*B+b][4H]
__device__ float g_xbuf0[(size_t)MROWS * H];    // 32 MB:  [t*B+b][H]
__device__ float g_xbuf1[(size_t)MROWS * H];    // 32 MB

// -------- helpers --------
__device__ __forceinline__ void ffma2(unsigned long long& d,
                                      unsigned long long a,
                                      unsigned long long b) {
    asm("fma.rn.f32x2 %0, %1, %2, %0;" : "+l"(d) : "l"(a), "l"(b));
}
__device__ __forceinline__ unsigned long long dup2(float a) {
    unsigned long long r;
    asm("mov.b64 %0, {%1, %1};" : "=l"(r) : "f"(a));
    return r;
}
__device__ __forceinline__ float2 unpack2(unsigned long long v) {
    float2 f;
    asm("mov.b64 {%0, %1}, %2;" : "=f"(f.x), "=f"(f.y) : "l"(v));
    return f;
}
__device__ __forceinline__ uint32_t smem_u32(const void* p) {
    return (uint32_t)__cvta_generic_to_shared(p);
}
__device__ __forceinline__ uint32_t ctarank() {
    uint32_t r;
    asm("mov.u32 %0, %%cluster_ctarank;" : "=r"(r));
    return r;
}
__device__ __forceinline__ uint32_t mapa_rank(uint32_t laddr, int r) {
    uint32_t ra;
    asm("mapa.shared::cluster.u32 %0, %1, %2;" : "=r"(ra) : "r"(laddr), "r"(r));
    return ra;
}
// fast, branch-free activations (rel err ~1e-6; saturate correctly)
__device__ __forceinline__ float fsigm(float x) {
    return __fdividef(1.0f, 1.0f + __expf(-x));
}
__device__ __forceinline__ float ftanh(float x) {
    return __fdividef(2.0f, 1.0f + __expf(-2.0f * x)) - 1.0f;
}
__device__ __forceinline__ void mbar_init(uint32_t a, int cnt) {
    asm volatile("mbarrier.init.shared.b64 [%0], %1;" :: "r"(a), "r"(cnt) : "memory");
}
__device__ __forceinline__ void mbar_expect(uint32_t a, uint32_t bytes) {
    asm volatile("mbarrier.arrive.expect_tx.shared.b64 _, [%0], %1;"
                 :: "r"(a), "r"(bytes) : "memory");
}
// st.async: data + completion bytes delivered to the DESTINATION CTA's
// mbarrier. No fence, no drain — the tx count IS the visibility guarantee.
__device__ __forceinline__ void st_async_b64(uint32_t dst, unsigned long long v,
                                             uint32_t rbar) {
    asm volatile(
        "st.async.weak.shared::cluster.mbarrier::complete_tx::bytes.b64 [%0], %1, [%2];"
        :: "r"(dst), "l"(v), "r"(rbar) : "memory");
}
__device__ __forceinline__ void mbar_wait(uint32_t a, uint32_t parity) {
    uint32_t done;
    asm volatile(
        "{\n\t.reg .pred p;\n\t"
        "mbarrier.try_wait.parity.acquire.cta.shared::cta.b64 p, [%1], %2;\n\t"
        "selp.b32 %0, 1, 0, p;\n\t}"
        : "=r"(done) : "r"(a), "r"(parity) : "memory");
    if (!done) {
        asm volatile(
            "{\n\t.reg .pred P1;\n\t"
            "W_%=:\n\t"
            "mbarrier.try_wait.parity.acquire.cta.shared::cta.b64 P1, [%0], %1, 0x989680;\n\t"
            "@P1 bra.uni D_%=;\n\t"
            "bra.uni W_%=;\n\t"
            "D_%=:\n\t}"
            :: "r"(a), "r"(parity) : "memory");
    }
}

// ============================================================
// GEMM: C[M=32768, N=1024] = A[M,256] @ W^T + bias
// BM=128, BN=128, BK=16, 256 threads, 8x8 microtile, FFMA2.
// ============================================================
__global__ void __launch_bounds__(256, 2)
lstm_gemm(const float* __restrict__ Aex, int asel,
          const float* __restrict__ Wl,
          const float* __restrict__ bl)
{
    const float* A = (asel == 0) ? Aex : (asel == 1 ? g_xbuf0 : g_xbuf1);
    float* Cout = g_gates;

    __shared__ __align__(16) float As[16][128];
    __shared__ __align__(16) float Bs[16][128];

    const int tid = threadIdx.x;
    const int n0 = blockIdx.x * 128;
    const int m0 = blockIdx.y * 128;
    const int tx = tid & 15, ty = tid >> 4;

    const int lr = tid >> 2;        // 0..63
    const int lk4 = tid & 3;        // 0..3

    unsigned long long acc[8][4];
#pragma unroll
    for (int i = 0; i < 8; i++)
#pragma unroll
        for (int j = 0; j < 4; j++) acc[i][j] = 0ull;

    const float* aP0 = A  + (size_t)(m0 + lr)      * 256 + lk4 * 4;
    const float* aP1 = A  + (size_t)(m0 + lr + 64) * 256 + lk4 * 4;
    const float* bP0 = Wl + (size_t)(n0 + lr)      * 256 + lk4 * 4;
    const float* bP1 = Wl + (size_t)(n0 + lr + 64) * 256 + lk4 * 4;

    float4 a0 = *(const float4*)(aP0);
    float4 a1 = *(const float4*)(aP1);
    float4 w0 = *(const float4*)(bP0);
    float4 w1 = *(const float4*)(bP1);

    for (int kt = 0; kt < 256; kt += 16) {
        __syncthreads();
        {
            int kb = lk4 * 4;
            As[kb + 0][lr] = a0.x; As[kb + 1][lr] = a0.y;
            As[kb + 2][lr] = a0.z; As[kb + 3][lr] = a0.w;
            As[kb + 0][lr + 64] = a1.x; As[kb + 1][lr + 64] = a1.y;
            As[kb + 2][lr + 64] = a1.z; As[kb + 3][lr + 64] = a1.w;
            Bs[kb + 0][lr] = w0.x; Bs[kb + 1][lr] = w0.y;
            Bs[kb + 2][lr] = w0.z; Bs[kb + 3][lr] = w0.w;
            Bs[kb + 0][lr + 64] = w1.x; Bs[kb + 1][lr + 64] = w1.y;
            Bs[kb + 2][lr + 64] = w1.z; Bs[kb + 3][lr + 64] = w1.w;
        }
        __syncthreads();

        if (kt < 240) {
            a0 = *(const float4*)(aP0 + kt + 16);
            a1 = *(const float4*)(aP1 + kt + 16);
            w0 = *(const float4*)(bP0 + kt + 16);
            w1 = *(const float4*)(bP1 + kt + 16);
        }

#pragma unroll
        for (int k = 0; k < 16; k++) {
            unsigned long long b2[4];
#pragma unroll
            for (int j = 0; j < 4; j++)
                b2[j] = *(const unsigned long long*)&Bs[k][tx * 8 + 2 * j];
            float4 af0 = *(const float4*)&As[k][ty * 8];
            float4 af1 = *(const float4*)&As[k][ty * 8 + 4];
            float a[8] = {af0.x, af0.y, af0.z, af0.w, af1.x, af1.y, af1.z, af1.w};
#pragma unroll
            for (int i = 0; i < 8; i++) {
                unsigned long long a2 = dup2(a[i]);
#pragma unroll
                for (int j = 0; j < 4; j++) ffma2(acc[i][j], a2, b2[j]);
            }
        }
    }

    float bias_r[8];
#pragma unroll
    for (int j = 0; j < 8; j++) bias_r[j] = bl[n0 + tx * 8 + j];
#pragma unroll
    for (int i = 0; i < 8; i++) {
        float o[8];
#pragma unroll
        for (int j = 0; j < 4; j++) {
            float2 v = unpack2(acc[i][j]);
            o[2 * j + 0] = v.x + bias_r[2 * j + 0];
            o[2 * j + 1] = v.y + bias_r[2 * j + 1];
        }
        float* crow = Cout + (size_t)(m0 + ty * 8 + i) * G4 + n0 + tx * 8;
        *(float4*)(crow + 0) = make_float4(o[0], o[1], o[2], o[3]);
        *(float4*)(crow + 4) = make_float4(o[4], o[5], o[6], o[7]);
    }
}

// ============================================================
// Recurrence scan. 16 clusters x 8 CTAs, 256 thr. Cluster owns
// batches {2c,2c+1}; CTA rank owns 32 h-indices x 4 gates (R in
// registers). Exchange = Round-12 st.async (proven fastest):
// 256 x 8-B st.async completing the destination's transaction
// mbarrier (2048 B), two barriers (even/odd step), expect_tx
// for t+1 posted before waiting on t, zero fences in the loop.
// NEW this round: gates_x staging (LDG->STS->LDS for all 256
// threads) deleted; only the 64 owner lanes prefetch their 4
// gate floats one step ahead into REGISTERS, so the pre-send
// syncthreads no longer waits on any DRAM access.
// ============================================================
__global__ void __launch_bounds__(256, 1) __cluster_dims__(8, 1, 1)
lstm_scan(const float* __restrict__ Rl,
          const float* __restrict__ h0,
          const float* __restrict__ c0,
          float* __restrict__ xex, int osel)
{
    float* xnext = (osel == 2) ? xex : (osel == 0 ? g_xbuf0 : g_xbuf1);
    const float* gates = g_gates;

    __shared__ __align__(16) float hs[2][2][H];        // buffer, batch, hidden
    __shared__ __align__(16) float hnew[2][32];        // batch, jj
    __shared__ __align__(8) unsigned long long mbars[2];  // even/odd step

    const int tid = threadIdx.x;
    const int rank = (int)ctarank();
    const int b0 = (blockIdx.x >> 3) * 2;
    const int sub = tid & 7;
    const int jj = tid >> 3;
    const int hidx = rank * 32 + jj;

    // ---- register-resident R slice: 4 gates x 16 column pairs ----
    unsigned long long Rf[4][16];
#pragma unroll
    for (int g = 0; g < 4; g++) {
        const float* base = Rl + (size_t)(g * 256 + hidx) * 256;
#pragma unroll
        for (int k2 = 0; k2 < 16; k2++)
            Rf[g][k2] = *(const unsigned long long*)(base + sub * 2 + 16 * k2);
    }

    // ---- initial h and c ----
    for (int i = tid; i < 2 * H; i += 256) {
        int b = i >> 8, idx = i & 255;
        hs[0][b][idx] = h0[(size_t)(b0 + b) * H + idx];
    }
    // epilogue split: lane sub==0 owns batch 0, sub==1 owns batch 1
    const int myb = sub;                 // meaningful for sub < 2
    const bool is_owner = (sub < 2);
    float creg = 0.f;
    if (is_owner) creg = c0[(size_t)(b0 + myb) * H + hidx];

    // owner-register gates: g_cur holds step t's 4 gate inputs
    const float* gbase = gates + (size_t)(b0 + myb) * G4 + hidx;  // + t*B*G4 + g*256
    float gcur[4] = {0.f, 0.f, 0.f, 0.f};
    if (is_owner) {
#pragma unroll
        for (int g = 0; g < 4; g++) gcur[g] = gbase[g * 256];     // t = 0
    }

    // ---- loop-invariant DSMEM addresses ----
    // broadcast role: warp w -> rank w; each thread one float2 (8 B)
    const int br = tid >> 5;
    const int bidx = tid & 31;
    const int bb = bidx >> 4, bj2 = bidx & 15;
    const uint32_t dstA = mapa_rank(smem_u32(&hs[1][bb][rank * 32 + bj2 * 2]), br);
    const uint32_t dstB = mapa_rank(smem_u32(&hs[0][bb][rank * 32 + bj2 * 2]), br);
    const uint32_t lmb0 = smem_u32((const void*)&mbars[0]);
    const uint32_t lmb1 = smem_u32((const void*)&mbars[1]);
    const uint32_t rmb0 = mapa_rank(lmb0, br);
    const uint32_t rmb1 = mapa_rank(lmb1, br);

    if (tid == 0) {
        mbar_init(lmb0, 1);
        mbar_init(lmb1, 1);
        mbar_expect(lmb0, 2048);   // expect for t = 0
    }
    __syncthreads();
    asm volatile("barrier.cluster.arrive.aligned;" ::: "memory");
    asm volatile("barrier.cluster.wait.aligned;" ::: "memory");

    int p = 0;
    for (int t = 0; t < S; t++) {
        // owner-only register prefetch of step t+1 gate inputs; consumed
        // next iteration -> covered by a full dot+reduce (~800 cyc), MLP=4
        float gnxt[4];
        if (is_owner) {
            const float* gp = gbase + (size_t)((t + 1 < S) ? (t + 1) : t) * (B * G4);
#pragma unroll
            for (int g = 0; g < 4; g++) gnxt[g] = gp[g * 256];
        }

        // ---- dot: acc[g][b] over this thread's 32 columns ----
        unsigned long long acc[4][2] = {{0ull, 0ull}, {0ull, 0ull},
                                        {0ull, 0ull}, {0ull, 0ull}};
        const float* hp0 = &hs[p][0][sub * 2];
        const float* hp1 = &hs[p][1][sub * 2];
#pragma unroll
        for (int k2 = 0; k2 < 16; k2++) {
            unsigned long long h0v = *(const unsigned long long*)(hp0 + 16 * k2);
            unsigned long long h1v = *(const unsigned long long*)(hp1 + 16 * k2);
#pragma unroll
            for (int g = 0; g < 4; g++) {
                ffma2(acc[g][0], Rf[g][k2], h0v);
                ffma2(acc[g][1], Rf[g][k2], h1v);
            }
        }

        // ---- reduce over the 8-lane column group ----
        float red[4][2];
#pragma unroll
        for (int g = 0; g < 4; g++)
#pragma unroll
            for (int b = 0; b < 2; b++) {
                float2 v = unpack2(acc[g][b]);
                float s = v.x + v.y;
                s += __shfl_xor_sync(0xffffffffu, s, 1);
                s += __shfl_xor_sync(0xffffffffu, s, 2);
                s += __shfl_xor_sync(0xffffffffu, s, 4);
                red[g][b] = s;
            }

        // ---- cell epilogue (two lanes per jj: sub==b, gates in regs) ----
        if (is_owner) {
            float gi = red[0][myb] + gcur[0];
            float gf = red[1][myb] + gcur[1];
            float gG = red[2][myb] + gcur[2];
            float go = red[3][myb] + gcur[3];
            float iv = fsigm(gi);
            float fv = fsigm(gf);
            float gv = ftanh(gG);
            float ov = fsigm(go);
            float cnew = fv * creg + iv * gv;
            creg = cnew;
            hnew[myb][jj] = ov * ftanh(cnew);
        }
#pragma unroll
        for (int g = 0; g < 4; g++) gcur[g] = gnxt[g];
        __syncthreads();   // hnew ready for broadcast

        // ---- st.async multicast: 64 new h floats -> all 8 ranks ----
        {
            unsigned long long v =
                *(const unsigned long long*)&hnew[bb][bj2 * 2];
            uint32_t dst = (p == 0) ? dstA : dstB;      // writes hs[p^1]
            uint32_t rb  = (t & 1) ? rmb1 : rmb0;       // step-t barrier
            st_async_b64(dst, v, rb);
        }
        // post expect for step t+1 NOW (guaranteed earlier than any peer's
        // t+1 bytes: those need our step-t bytes + a full peer step first)
        if (tid == 0) mbar_expect((t & 1) ? lmb0 : lmb1, 2048);

        // global write of this CTA's h slice (off all sync paths)
        if (tid < 16) {
            int b = tid >> 3, q = tid & 7;
            float4 v = ((const float4*)&hnew[b][0])[q];
            *(float4*)&xnext[(size_t)(t * B + b0 + b) * H + rank * 32 + q * 4] = v;
        }

        // wait for all 2048 B of step t to land in hs[p^1]
        mbar_wait((t & 1) ? lmb1 : lmb0, (uint32_t)((t >> 1) & 1));
        p ^= 1;
    }

    // keep smem alive until every peer's last st.async has landed
    asm volatile("barrier.cluster.arrive.aligned;" ::: "memory");
    asm volatile("barrier.cluster.wait.aligned;" ::: "memory");
}

// ============================================================
// Host: 4 x (GEMM, SCAN), ping-pong x buffers, all on stream 0.
// ============================================================
extern "C" void kernel_launch(void* const* d_in, const int* in_sizes, int n_in,
                              void* d_out, int out_size)
{
    const float* h_data = (const float*)d_in[0];
    const float* x_data = (const float*)d_in[1];
    const float* c_data = (const float*)d_in[2];
    const float* W      = (const float*)d_in[3];
    const float* R      = (const float*)d_in[4];
    const float* bias   = (const float*)d_in[5];
    float* out = (float*)d_out;

    const dim3 ggrid(8, 256);               // N/128, M/128
    const size_t wstride = (size_t)G4 * H;

    lstm_gemm<<<ggrid, 256>>>(x_data, 0, W + 0 * wstride, bias + 0 * G4);
    lstm_scan<<<128, 256>>>(R + 0 * wstride,
                            h_data + 0 * (size_t)LSTRIDE,
                            c_data + 0 * (size_t)LSTRIDE,
                            nullptr, 0);
    lstm_gemm<<<ggrid, 256>>>(nullptr, 1, W + 1 * wstride, bias + 1 * G4);
    lstm_scan<<<128, 256>>>(R + 1 * wstride,
                            h_data + 1 * (size_t)LSTRIDE,
                            c_data + 1 * (size_t)LSTRIDE,
                            nullptr, 1);
    lstm_gemm<<<ggrid, 256>>>(nullptr, 2, W + 2 * wstride, bias + 2 * G4);
    lstm_scan<<<128, 256>>>(R + 2 * wstride,
                            h_data + 2 * (size_t)LSTRIDE,
                            c_data + 2 * (size_t)LSTRIDE,
                            nullptr, 0);
    lstm_gemm<<<ggrid, 256>>>(nullptr, 1, W + 3 * wstride, bias + 3 * G4);
    lstm_scan<<<128, 256>>>(R + 3 * wstride,
                            h_data + 3 * (size_t)LSTRIDE,
                            c_data + 3 * (size_t)LSTRIDE,
                            out, 2);
}